// round 16
// baseline (speedup 1.0000x reference)
#include <cuda_runtime.h>
#include <cuda_fp16.h>
#include <cstdint>

// Problem constants
#define Bb     8
#define Ll     4096
#define Dd     1024
#define Hh     16
#define BLK    4
#define HDIM   64
#define MTOT   (Bb*Ll)        // 32768
#define NQKV   (3*Dd)         // 3072

// Scratch (no cudaMalloc allowed)
__device__ __half g_qkvh[100663296]; // qkv in fp16
__device__ __half g_oh[33554432];    // attention out, fp16
__device__ __half g_xh[33554432];    // x in fp16
__device__ __half g_wqh[3145728];    // W_qkv^T [3072][1024] fp16
__device__ __half g_wph[1048576];    // W_proj^T [1024][1024] fp16

// ---------------------------------------------------------------------------
__device__ __forceinline__ uint32_t smem_u32(const void* p) {
    uint32_t a;
    asm("{ .reg .u64 t; cvta.to.shared.u64 t, %1; cvt.u32.u64 %0, t; }" : "=r"(a) : "l"(p));
    return a;
}

__device__ __forceinline__ void cpasync16(uint32_t dst, const void* src) {
    asm volatile("cp.async.cg.shared.global [%0], [%1], 16;" :: "r"(dst), "l"(src));
}

#define MBAR_INIT(a, c) \
    asm volatile("mbarrier.init.shared.b64 [%0], %1;" :: "r"(a), "r"(c) : "memory")
#define MBAR_ARRIVE(a) \
    asm volatile("mbarrier.arrive.shared.b64 _, [%0];" :: "r"(a) : "memory")
// .noinc: barrier init count already accounts for these arrivals
#define CPASYNC_MBAR_ARRIVE(a) \
    asm volatile("cp.async.mbarrier.arrive.noinc.shared::cta.b64 [%0];" :: "r"(a) : "memory")

#define MBAR_WAIT(a, ph) do {                                                   \
    uint32_t _m = (a), _p = (ph), _d;                                           \
    asm volatile("{\n .reg .pred p;\n"                                          \
        " mbarrier.try_wait.parity.acquire.cta.shared::cta.b64 p, [%1], %2;\n"  \
        " selp.b32 %0, 1, 0, p;\n}" : "=r"(_d) : "r"(_m), "r"(_p) : "memory");  \
    if (!_d) {                                                                  \
        asm volatile("{\n .reg .pred P1;\n"                                     \
        "WL_%=:\n"                                                              \
        " mbarrier.try_wait.parity.acquire.cta.shared::cta.b64 P1, [%0], %1, 0x989680;\n" \
        " @P1 bra.uni WD_%=;\n bra.uni WL_%=;\nWD_%=:\n}"                      \
        :: "r"(_m), "r"(_p) : "memory");                                        \
    }                                                                           \
} while (0)

// fp16 MMA, f32 accumulate: m16n8k16
__device__ __forceinline__ void mma_f16(float c[4], const uint32_t a[4], const uint32_t b[2]) {
    asm volatile(
        "mma.sync.aligned.m16n8k16.row.col.f32.f16.f16.f32 "
        "{%0,%1,%2,%3}, {%4,%5,%6,%7}, {%8,%9}, {%0,%1,%2,%3};\n"
        : "+f"(c[0]), "+f"(c[1]), "+f"(c[2]), "+f"(c[3])
        : "r"(a[0]), "r"(a[1]), "r"(a[2]), "r"(a[3]),
          "r"(b[0]), "r"(b[1]));
}

// ---------------------------------------------------------------------------
// Prologue kernels
// ---------------------------------------------------------------------------
__global__ __launch_bounds__(256)
void f2h_kernel(const float4* __restrict__ in, uint2* __restrict__ out, int n4)
{
    int i = blockIdx.x * blockDim.x + threadIdx.x;
    int stride = gridDim.x * blockDim.x;
    for (; i < n4; i += stride) {
        float4 v = in[i];
        __half2 lo = __floats2half2_rn(v.x, v.y);
        __half2 hi = __floats2half2_rn(v.z, v.w);
        uint2 u;
        u.x = *reinterpret_cast<uint32_t*>(&lo);
        u.y = *reinterpret_cast<uint32_t*>(&hi);
        out[i] = u;
    }
}

__global__ __launch_bounds__(256)
void transpose_h_kernel(const float* __restrict__ in, __half* __restrict__ out,
                        int K, int N)
{
    __shared__ float t[32][33];
    const int n0 = blockIdx.x * 32;
    const int k0 = blockIdx.y * 32;
    const int tx = threadIdx.x & 31;
    const int ty = threadIdx.x >> 5;
#pragma unroll
    for (int j = 0; j < 4; ++j)
        t[ty + j * 8][tx] = in[(size_t)(k0 + ty + j * 8) * N + n0 + tx];
    __syncthreads();
#pragma unroll
    for (int j = 0; j < 4; ++j)
        out[(size_t)(n0 + ty + j * 8) * K + k0 + tx] = __float2half_rn(t[tx][ty + j * 8]);
}

// ---------------------------------------------------------------------------
// Warp-specialized FP16 GEMM (mma.sync m16n8k16, f32 accum).
// CTA 128(M) x 128(N), BK=64, 320 threads: warps 0-7 consumers in a 4M x 2N
// grid with 32(M) x 64(N) warp tiles (A dup x2, B dup x4 -> 251 L1-bytes/MMA
// vs 352 in the 32x32 config), warps 8-9 producers (coalesced). 3-stage ring
// with full/empty mbarriers; no __syncthreads in mainloop. 2 CTAs/SM
// (20 warps). A [M][K], Bt [N][K] fp16 row-major; 128B rows, SW128 swizzle.
// OutT = float or __half. Requires M%128==0, N%128==0, K%64==0.
// ---------------------------------------------------------------------------
#define A_TILE  16384
#define B_TILE  16384
#define STAGE_B (A_TILE + B_TILE)      // 32768
#define STAGES  3
#define GEMM_SMEM (STAGES * STAGE_B + 64)
#define BKC 64

template<typename OutT>
__global__ __launch_bounds__(320, 2)
void gemm_ws_kernel(const __half* __restrict__ A, const __half* __restrict__ Bt,
                    const float* __restrict__ bias, OutT* __restrict__ C,
                    int N, int K)
{
    extern __shared__ char dsm[];
    const uint32_t sbase = smem_u32(dsm);
    const uint32_t mbarB = sbase + STAGES * STAGE_B;   // full[s]=+16s, empty[s]=+16s+8

    const int tid  = threadIdx.x;
    const int wid  = tid >> 5;
    const int lane = tid & 31;

    const int m0 = blockIdx.y * 128;
    const int n0 = blockIdx.x * 128;
    const int NC = K >> 6;

    if (tid == 0) {
#pragma unroll
        for (int s = 0; s < STAGES; ++s) {
            MBAR_INIT(mbarB + s * 16,     64);   // full: 64 producer threads (.noinc cp-arrive)
            MBAR_INIT(mbarB + s * 16 + 8, 256);  // empty: 256 consumer threads
        }
    }
    __syncthreads();

    if (wid >= 8) {
        // ================= PRODUCER (64 threads, coalesced) =================
        const int pt  = tid - 256;     // 0..63
        const int k16 = pt & 7;        // fixed 16B chunk within 128B row
        const int rg  = pt >> 3;       // 0..7 row group
        const char* aP = (const char*)A  + ((size_t)(m0 + rg) * K + k16 * 8) * 2;
        const char* bP = (const char*)Bt + ((size_t)(n0 + rg) * K + k16 * 8) * 2;
        const uint32_t sx = (uint32_t)((k16 ^ rg) << 4);
        const uint32_t aRel = (uint32_t)rg * 128 + sx;            // +1024 per 8 rows
        const uint32_t bRel = (uint32_t)rg * 128 + sx + A_TILE;
        const size_t rowStep = (size_t)(8 * K) * 2;               // 8 rows in bytes

        int ph = 1;   // producer starts flipped: first empty-waits pass
        for (int c = 0; c < NC; ++c) {
            const int s = c % 3;
            MBAR_WAIT(mbarB + s * 16 + 8, ph);
            if (s == 2) ph ^= 1;
            const uint32_t base = sbase + s * STAGE_B;
            {   // A: 128 rows (rg + 8*it)
                const char* p = aP;
                uint32_t d = base + aRel;
#pragma unroll
                for (int it = 0; it < 16; ++it) {
                    cpasync16(d, p);
                    p += rowStep; d += 1024;
                }
            }
            {   // B: 128 rows
                const char* p = bP;
                uint32_t d = base + bRel;
#pragma unroll
                for (int it = 0; it < 16; ++it) {
                    cpasync16(d, p);
                    p += rowStep; d += 1024;
                }
            }
            CPASYNC_MBAR_ARRIVE(mbarB + s * 16);
            aP += BKC * 2; bP += BKC * 2;
        }
        return;
    }

    // ================= CONSUMER (8 warps, 256 threads) =================
    const int warpM = wid & 3;       // 4 groups of 32 rows
    const int warpN = wid >> 2;      // 2 groups of 64 cols

    // fp16 16816 ldmatrix.x4 mapping
    const int r8  = lane & 7;
    const int sel = lane >> 3;
    const int rowAdd = r8 + ((sel & 1) << 3);
    const int colAdd = sel >> 1;
    uint32_t colPart[4];
#pragma unroll
    for (int ks = 0; ks < 4; ++ks)
        colPart[ks] = (uint32_t)(((2 * ks + colAdd) ^ r8) << 4);

    uint32_t aRow[2], bRow[4];
#pragma unroll
    for (int g = 0; g < 2; ++g)
        aRow[g] = (uint32_t)(warpM * 32 + g * 16 + rowAdd) * 128;
#pragma unroll
    for (int j = 0; j < 4; ++j)
        bRow[j] = (uint32_t)(warpN * 64 + j * 16 + rowAdd) * 128 + A_TILE;

    float acc[2][8][4];
#pragma unroll
    for (int mt = 0; mt < 2; ++mt)
#pragma unroll
        for (int nt = 0; nt < 8; ++nt)
#pragma unroll
            for (int r = 0; r < 4; ++r) acc[mt][nt][r] = 0.0f;

    uint32_t aF[2][4], bF[8][2];

    int ph = 0;
    for (int c = 0; c < NC; ++c) {
        const int s = c % 3;
        MBAR_WAIT(mbarB + s * 16, ph);
        if (s == 2) ph ^= 1;
        const uint32_t sB = sbase + s * STAGE_B;

#pragma unroll
        for (int ks = 0; ks < 4; ++ks) {
            const uint32_t cp = colPart[ks];
#pragma unroll
            for (int mt = 0; mt < 2; ++mt) {
                asm volatile("ldmatrix.sync.aligned.m8n8.x4.shared.b16 {%0,%1,%2,%3}, [%4];"
                             : "=r"(aF[mt][0]), "=r"(aF[mt][1]),
                               "=r"(aF[mt][2]), "=r"(aF[mt][3])
                             : "r"(sB + aRow[mt] + cp));
            }
#pragma unroll
            for (int j = 0; j < 4; ++j) {
                uint32_t r0, r1, r2, r3;
                asm volatile("ldmatrix.sync.aligned.m8n8.x4.shared.b16 {%0,%1,%2,%3}, [%4];"
                             : "=r"(r0), "=r"(r1), "=r"(r2), "=r"(r3)
                             : "r"(sB + bRow[j] + cp));
                bF[j * 2][0]     = r0; bF[j * 2][1]     = r2;
                bF[j * 2 + 1][0] = r1; bF[j * 2 + 1][1] = r3;
            }
#pragma unroll
            for (int mt = 0; mt < 2; ++mt)
#pragma unroll
                for (int nt = 0; nt < 8; ++nt)
                    mma_f16(acc[mt][nt], aF[mt], bF[nt]);
        }
        MBAR_ARRIVE(mbarB + s * 16 + 8);
    }

    // ---- epilogue: bias + store ----
    const int col0 = n0 + warpN * 64 + 2 * (lane & 3);
    float2 bv[8];
#pragma unroll
    for (int nt = 0; nt < 8; ++nt)
        bv[nt] = *(const float2*)(bias + col0 + nt * 8);

    const int row0 = m0 + warpM * 32 + (lane >> 2);
#pragma unroll
    for (int mt = 0; mt < 2; ++mt) {
        int r = row0 + mt * 16;
#pragma unroll
        for (int nt = 0; nt < 8; ++nt) {
            int cc = col0 + nt * 8;
            float x0 = acc[mt][nt][0] + bv[nt].x;
            float y0 = acc[mt][nt][1] + bv[nt].y;
            float x1 = acc[mt][nt][2] + bv[nt].x;
            float y1 = acc[mt][nt][3] + bv[nt].y;
            if constexpr (sizeof(OutT) == 4) {
                *(float2*)((float*)C + (size_t)r * N + cc)       = make_float2(x0, y0);
                *(float2*)((float*)C + (size_t)(r + 8) * N + cc) = make_float2(x1, y1);
            } else {
                *(__half2*)((__half*)C + (size_t)r * N + cc)       = __floats2half2_rn(x0, y0);
                *(__half2*)((__half*)C + (size_t)(r + 8) * N + cc) = __floats2half2_rn(x1, y1);
            }
        }
    }
}

// ---------------------------------------------------------------------------
// Block attention: one warp per (b, h, block). BS=4, d=64. fp16 in/out.
// ---------------------------------------------------------------------------
__global__ __launch_bounds__(256)
void block_attn_kernel(const __half* __restrict__ qkv, __half* __restrict__ o)
{
    const int gwarp = (blockIdx.x * blockDim.x + threadIdx.x) >> 5;
    const int lane  = threadIdx.x & 31;

    const int nb = gwarp & 1023;
    const int bh = gwarp >> 10;
    const int h  = bh & 15;
    const int b  = bh >> 4;
    const int l0 = nb * BLK;

    const size_t rowBase = ((size_t)(b * Ll + l0)) * NQKV + h * 192;

    float2 q[4], k[4], v[4];
#pragma unroll
    for (int i = 0; i < 4; ++i) {
        const __half* p = qkv + rowBase + (size_t)i * NQKV + 2 * lane;
        q[i] = __half22float2(*(const __half2*)(p));
        k[i] = __half22float2(*(const __half2*)(p + 64));
        v[i] = __half22float2(*(const __half2*)(p + 128));
    }

    float s[4][4];
#pragma unroll
    for (int i = 0; i < 4; ++i)
#pragma unroll
        for (int j = 0; j < 4; ++j)
            s[i][j] = fmaf(q[i].y, k[j].y, q[i].x * k[j].x);

#pragma unroll
    for (int i = 0; i < 4; ++i)
#pragma unroll
        for (int j = 0; j < 4; ++j)
#pragma unroll
            for (int off = 16; off > 0; off >>= 1)
                s[i][j] += __shfl_xor_sync(0xffffffffu, s[i][j], off);

    const float scale = 0.125f;
    const size_t obase = ((size_t)(b * Ll + l0)) * Dd + h * HDIM + 2 * lane;
#pragma unroll
    for (int i = 0; i < 4; ++i) {
        float t0 = s[i][0] * scale, t1 = s[i][1] * scale;
        float t2 = s[i][2] * scale, t3 = s[i][3] * scale;
        float m = fmaxf(fmaxf(t0, t1), fmaxf(t2, t3));
        float e0 = __expf(t0 - m), e1 = __expf(t1 - m);
        float e2 = __expf(t2 - m), e3 = __expf(t3 - m);
        float inv = 1.0f / (e0 + e1 + e2 + e3);
        float p0 = e0 * inv, p1 = e1 * inv, p2 = e2 * inv, p3 = e3 * inv;
        float ox = p0 * v[0].x; ox = fmaf(p1, v[1].x, ox);
        ox = fmaf(p2, v[2].x, ox); ox = fmaf(p3, v[3].x, ox);
        float oy = p0 * v[0].y; oy = fmaf(p1, v[1].y, oy);
        oy = fmaf(p2, v[2].y, oy); oy = fmaf(p3, v[3].y, oy);
        *(__half2*)(o + obase + (size_t)i * Dd) = __floats2half2_rn(ox, oy);
    }
}

// ---------------------------------------------------------------------------
extern "C" void kernel_launch(void* const* d_in, const int* in_sizes, int n_in,
                              void* d_out, int out_size)
{
    const float* x     = (const float*)d_in[0];
    const float* Wqkv  = (const float*)d_in[1];
    const float* bqkv  = (const float*)d_in[2];
    const float* Wproj = (const float*)d_in[3];
    const float* bproj = (const float*)d_in[4];
    float* out = (float*)d_out;

    __half *qkvh, *oh, *xh, *wqh, *wph;
    cudaGetSymbolAddress((void**)&qkvh, g_qkvh);
    cudaGetSymbolAddress((void**)&oh,   g_oh);
    cudaGetSymbolAddress((void**)&xh,   g_xh);
    cudaGetSymbolAddress((void**)&wqh,  g_wqh);
    cudaGetSymbolAddress((void**)&wph,  g_wph);

    cudaFuncSetAttribute(gemm_ws_kernel<__half>,
                         cudaFuncAttributeMaxDynamicSharedMemorySize, GEMM_SMEM);
    cudaFuncSetAttribute(gemm_ws_kernel<float>,
                         cudaFuncAttributeMaxDynamicSharedMemorySize, GEMM_SMEM);

    // 0) x -> fp16; weights -> transposed fp16 (Wt[N][K])
    f2h_kernel<<<8192, 256>>>((const float4*)x, (uint2*)xh, MTOT * Dd / 4);
    {
        dim3 g1(NQKV / 32, Dd / 32);
        transpose_h_kernel<<<g1, 256>>>(Wqkv, wqh, Dd, NQKV);
        dim3 g2(Dd / 32, Dd / 32);
        transpose_h_kernel<<<g2, 256>>>(Wproj, wph, Dd, Dd);
    }

    // 1) qkv = x @ W_qkv + b_qkv  (fp16 out)
    {
        dim3 grid(NQKV / 128, MTOT / 128);
        gemm_ws_kernel<__half><<<grid, 320, GEMM_SMEM>>>(xh, wqh, bqkv, qkvh, NQKV, Dd);
    }

    // 2) block attention (fp16 in/out)
    {
        int nwarps = Bb * Hh * (Ll / BLK);
        block_attn_kernel<<<nwarps / 8, 256>>>(qkvh, oh);
    }

    // 3) out = o @ W_proj + b_proj  (f32 out)
    {
        dim3 grid(Dd / 128, MTOT / 128);
        gemm_ws_kernel<float><<<grid, 320, GEMM_SMEM>>>(oh, wph, bproj, out, Dd, Dd);
    }
}

// round 17
// speedup vs baseline: 1.1176x; 1.1176x over previous
#include <cuda_runtime.h>
#include <cuda_fp16.h>
#include <cstdint>

// Problem constants
#define Bb     8
#define Ll     4096
#define Dd     1024
#define Hh     16
#define BLK    4
#define HDIM   64
#define MTOT   (Bb*Ll)        // 32768
#define NQKV   (3*Dd)         // 3072

// Scratch (no cudaMalloc allowed)
__device__ __half g_oh[33554432];    // attention out, fp16
__device__ __half g_xh[33554432];    // x in fp16
__device__ __half g_wqh[3145728];    // W_qkv^T [3072][1024] fp16
__device__ __half g_wph[1048576];    // W_proj^T [1024][1024] fp16

// ---------------------------------------------------------------------------
__device__ __forceinline__ uint32_t smem_u32(const void* p) {
    uint32_t a;
    asm("{ .reg .u64 t; cvta.to.shared.u64 t, %1; cvt.u32.u64 %0, t; }" : "=r"(a) : "l"(p));
    return a;
}

__device__ __forceinline__ void cpasync16(uint32_t dst, const void* src) {
    asm volatile("cp.async.cg.shared.global [%0], [%1], 16;" :: "r"(dst), "l"(src));
}

#define MBAR_INIT(a, c) \
    asm volatile("mbarrier.init.shared.b64 [%0], %1;" :: "r"(a), "r"(c) : "memory")
#define MBAR_ARRIVE(a) \
    asm volatile("mbarrier.arrive.shared.b64 _, [%0];" :: "r"(a) : "memory")
// .noinc: barrier init count already accounts for these arrivals
#define CPASYNC_MBAR_ARRIVE(a) \
    asm volatile("cp.async.mbarrier.arrive.noinc.shared::cta.b64 [%0];" :: "r"(a) : "memory")

#define MBAR_WAIT(a, ph) do {                                                   \
    uint32_t _m = (a), _p = (ph), _d;                                           \
    asm volatile("{\n .reg .pred p;\n"                                          \
        " mbarrier.try_wait.parity.acquire.cta.shared::cta.b64 p, [%1], %2;\n"  \
        " selp.b32 %0, 1, 0, p;\n}" : "=r"(_d) : "r"(_m), "r"(_p) : "memory");  \
    if (!_d) {                                                                  \
        asm volatile("{\n .reg .pred P1;\n"                                     \
        "WL_%=:\n"                                                              \
        " mbarrier.try_wait.parity.acquire.cta.shared::cta.b64 P1, [%0], %1, 0x989680;\n" \
        " @P1 bra.uni WD_%=;\n bra.uni WL_%=;\nWD_%=:\n}"                      \
        :: "r"(_m), "r"(_p) : "memory");                                        \
    }                                                                           \
} while (0)

// fp16 MMA, f32 accumulate: m16n8k16
__device__ __forceinline__ void mma_f16(float c[4], const uint32_t a[4], const uint32_t b[2]) {
    asm volatile(
        "mma.sync.aligned.m16n8k16.row.col.f32.f16.f16.f32 "
        "{%0,%1,%2,%3}, {%4,%5,%6,%7}, {%8,%9}, {%0,%1,%2,%3};\n"
        : "+f"(c[0]), "+f"(c[1]), "+f"(c[2]), "+f"(c[3])
        : "r"(a[0]), "r"(a[1]), "r"(a[2]), "r"(a[3]),
          "r"(b[0]), "r"(b[1]));
}

// ---------------------------------------------------------------------------
// Prologue kernels
// ---------------------------------------------------------------------------
__global__ __launch_bounds__(256)
void f2h_kernel(const float4* __restrict__ in, uint2* __restrict__ out, int n4)
{
    int i = blockIdx.x * blockDim.x + threadIdx.x;
    int stride = gridDim.x * blockDim.x;
    for (; i < n4; i += stride) {
        float4 v = in[i];
        __half2 lo = __floats2half2_rn(v.x, v.y);
        __half2 hi = __floats2half2_rn(v.z, v.w);
        uint2 u;
        u.x = *reinterpret_cast<uint32_t*>(&lo);
        u.y = *reinterpret_cast<uint32_t*>(&hi);
        out[i] = u;
    }
}

__global__ __launch_bounds__(256)
void transpose_h_kernel(const float* __restrict__ in, __half* __restrict__ out,
                        int K, int N)
{
    __shared__ float t[32][33];
    const int n0 = blockIdx.x * 32;
    const int k0 = blockIdx.y * 32;
    const int tx = threadIdx.x & 31;
    const int ty = threadIdx.x >> 5;
#pragma unroll
    for (int j = 0; j < 4; ++j)
        t[ty + j * 8][tx] = in[(size_t)(k0 + ty + j * 8) * N + n0 + tx];
    __syncthreads();
#pragma unroll
    for (int j = 0; j < 4; ++j)
        out[(size_t)(n0 + ty + j * 8) * K + k0 + tx] = __float2half_rn(t[tx][ty + j * 8]);
}

// ---------------------------------------------------------------------------
// FUSED qkv GEMM + block attention.
// CTA tile 64(M) x 192(N) where 192 = one head's [q|k|v]. Grid (16 heads,
// 512 M-tiles). 320 threads: warps 0-7 consumers (32x48 tiles, 2M x 4N),
// warps 8-9 producers. 3-stage mbarrier ring (WS, no __syncthreads in loop).
// Epilogue: acc+bias -> smem fp16 (64x192), bar.sync(1,256), each warp runs
// softmax-attention on 2 blocks (BS=4, d=64) and writes o[b,l,h*64+..] fp16.
// 2 CTAs/SM. K=1024 fixed.
// ---------------------------------------------------------------------------
#define FA_TILE  8192                   // 64 rows x 128B
#define FB_TILE  24576                  // 192 rows x 128B
#define FSTAGE   (FA_TILE + FB_TILE)    // 32768
#define FSTAGES  3
#define FUSED_SMEM (FSTAGES * FSTAGE + 64)
#define BKC 64

__global__ __launch_bounds__(320, 2)
void qkv_attn_fused_kernel(const __half* __restrict__ A, const __half* __restrict__ Bt,
                           const float* __restrict__ bias, __half* __restrict__ O)
{
    extern __shared__ char dsm[];
    const uint32_t sbase = smem_u32(dsm);
    const uint32_t mbarB = sbase + FSTAGES * FSTAGE;  // full[s]=+16s, empty[s]=+16s+8

    const int tid  = threadIdx.x;
    const int wid  = tid >> 5;
    const int lane = tid & 31;

    const int head = blockIdx.x;
    const int n0   = head * 192;
    const int m0   = blockIdx.y * 64;
    const int NC   = Dd >> 6;            // 16

    if (tid == 0) {
#pragma unroll
        for (int s = 0; s < FSTAGES; ++s) {
            MBAR_INIT(mbarB + s * 16,     64);   // full (producer .noinc cp-arrive)
            MBAR_INIT(mbarB + s * 16 + 8, 256);  // empty (consumers)
        }
    }
    __syncthreads();

    if (wid >= 8) {
        // ============ PRODUCER (64 threads, coalesced) ============
        const int pt  = tid - 256;
        const int k16 = pt & 7;
        const int rg  = pt >> 3;             // 0..7
        const char* aP = (const char*)A  + ((size_t)(m0 + rg) * Dd + k16 * 8) * 2;
        const char* bP = (const char*)Bt + ((size_t)(n0 + rg) * Dd + k16 * 8) * 2;
        const uint32_t sx = (uint32_t)((k16 ^ rg) << 4);
        const uint32_t aRel = (uint32_t)rg * 128 + sx;
        const uint32_t bRel = (uint32_t)rg * 128 + sx + FA_TILE;
        const size_t rowStep = (size_t)(8 * Dd) * 2;

        int ph = 1;
        for (int c = 0; c < NC; ++c) {
            const int s = c % 3;
            MBAR_WAIT(mbarB + s * 16 + 8, ph);
            if (s == 2) ph ^= 1;
            const uint32_t base = sbase + s * FSTAGE;
            {   // A: 64 rows
                const char* p = aP;
                uint32_t d = base + aRel;
#pragma unroll
                for (int it = 0; it < 8; ++it) { cpasync16(d, p); p += rowStep; d += 1024; }
            }
            {   // B: 192 rows
                const char* p = bP;
                uint32_t d = base + bRel;
#pragma unroll
                for (int it = 0; it < 24; ++it) { cpasync16(d, p); p += rowStep; d += 1024; }
            }
            CPASYNC_MBAR_ARRIVE(mbarB + s * 16);
            aP += BKC * 2; bP += BKC * 2;
        }
        return;   // producers exit; later syncs are named-barrier(1, 256)
    }

    // ============ CONSUMER (8 warps, 256 threads) ============
    const int warpM = wid & 1;        // 2 groups of 32 rows
    const int warpN = wid >> 1;       // 4 groups of 48 cols

    const int r8  = lane & 7;
    const int sel = lane >> 3;
    const int rowAdd = r8 + ((sel & 1) << 3);
    const int colAdd = sel >> 1;
    uint32_t colPart[4];
#pragma unroll
    for (int ks = 0; ks < 4; ++ks)
        colPart[ks] = (uint32_t)(((2 * ks + colAdd) ^ r8) << 4);

    uint32_t aRow[2], bRow[3];
#pragma unroll
    for (int g = 0; g < 2; ++g)
        aRow[g] = (uint32_t)(warpM * 32 + g * 16 + rowAdd) * 128;
#pragma unroll
    for (int j = 0; j < 3; ++j)
        bRow[j] = (uint32_t)(warpN * 48 + j * 16 + rowAdd) * 128 + FA_TILE;

    float acc[2][6][4];
#pragma unroll
    for (int mt = 0; mt < 2; ++mt)
#pragma unroll
        for (int nt = 0; nt < 6; ++nt)
#pragma unroll
            for (int r = 0; r < 4; ++r) acc[mt][nt][r] = 0.0f;

    uint32_t aF[2][4], bF[6][2];

    int ph = 0;
    for (int c = 0; c < NC; ++c) {
        const int s = c % 3;
        MBAR_WAIT(mbarB + s * 16, ph);
        if (s == 2) ph ^= 1;
        const uint32_t sB = sbase + s * FSTAGE;

#pragma unroll
        for (int ks = 0; ks < 4; ++ks) {
            const uint32_t cp = colPart[ks];
#pragma unroll
            for (int mt = 0; mt < 2; ++mt) {
                asm volatile("ldmatrix.sync.aligned.m8n8.x4.shared.b16 {%0,%1,%2,%3}, [%4];"
                             : "=r"(aF[mt][0]), "=r"(aF[mt][1]),
                               "=r"(aF[mt][2]), "=r"(aF[mt][3])
                             : "r"(sB + aRow[mt] + cp));
            }
#pragma unroll
            for (int j = 0; j < 3; ++j) {
                uint32_t r0, r1, r2, r3;
                asm volatile("ldmatrix.sync.aligned.m8n8.x4.shared.b16 {%0,%1,%2,%3}, [%4];"
                             : "=r"(r0), "=r"(r1), "=r"(r2), "=r"(r3)
                             : "r"(sB + bRow[j] + cp));
                bF[j * 2][0]     = r0; bF[j * 2][1]     = r2;
                bF[j * 2 + 1][0] = r1; bF[j * 2 + 1][1] = r3;
            }
#pragma unroll
            for (int mt = 0; mt < 2; ++mt)
#pragma unroll
                for (int nt = 0; nt < 6; ++nt)
                    mma_f16(acc[mt][nt], aF[mt], bF[nt]);
        }
        MBAR_ARRIVE(mbarB + s * 16 + 8);
    }

    // ===== epilogue part 1: acc + bias -> smem fp16 [64 rows x 192 cols] =====
    asm volatile("bar.sync 1, 256;" ::: "memory");   // consumers only

    const int col0 = warpN * 48 + 2 * (lane & 3);
    const int row0 = warpM * 32 + (lane >> 2);
#pragma unroll
    for (int nt = 0; nt < 6; ++nt) {
        int cc = col0 + nt * 8;
        float2 bv = *(const float2*)(bias + n0 + cc);
#pragma unroll
        for (int mt = 0; mt < 2; ++mt) {
            int r = row0 + mt * 16;
            __half2 h0 = __floats2half2_rn(acc[mt][nt][0] + bv.x, acc[mt][nt][1] + bv.y);
            __half2 h1 = __floats2half2_rn(acc[mt][nt][2] + bv.x, acc[mt][nt][3] + bv.y);
            *(__half2*)(dsm + r * 384 + cc * 2)       = h0;
            *(__half2*)(dsm + (r + 8) * 384 + cc * 2) = h1;
        }
    }
    asm volatile("bar.sync 1, 256;" ::: "memory");

    // ===== epilogue part 2: attention on 2 blocks per warp =====
#pragma unroll
    for (int jb = 0; jb < 2; ++jb) {
        const int blk = wid * 2 + jb;         // 0..15
        const int r0 = blk * 4;               // rows r0..r0+3

        float2 q[4], k[4], v[4];
#pragma unroll
        for (int i = 0; i < 4; ++i) {
            const char* rp = dsm + (r0 + i) * 384 + 4 * lane;
            q[i] = __half22float2(*(const __half2*)(rp));
            k[i] = __half22float2(*(const __half2*)(rp + 128));
            v[i] = __half22float2(*(const __half2*)(rp + 256));
        }

        float s[4][4];
#pragma unroll
        for (int i = 0; i < 4; ++i)
#pragma unroll
            for (int j = 0; j < 4; ++j)
                s[i][j] = fmaf(q[i].y, k[j].y, q[i].x * k[j].x);

#pragma unroll
        for (int i = 0; i < 4; ++i)
#pragma unroll
            for (int j = 0; j < 4; ++j)
#pragma unroll
                for (int off = 16; off > 0; off >>= 1)
                    s[i][j] += __shfl_xor_sync(0xffffffffu, s[i][j], off);

        const float scale = 0.125f;
        const size_t gRow0 = (size_t)(m0 + r0);
#pragma unroll
        for (int i = 0; i < 4; ++i) {
            float t0 = s[i][0] * scale, t1 = s[i][1] * scale;
            float t2 = s[i][2] * scale, t3 = s[i][3] * scale;
            float m = fmaxf(fmaxf(t0, t1), fmaxf(t2, t3));
            float e0 = __expf(t0 - m), e1 = __expf(t1 - m);
            float e2 = __expf(t2 - m), e3 = __expf(t3 - m);
            float inv = 1.0f / (e0 + e1 + e2 + e3);
            float p0 = e0 * inv, p1 = e1 * inv, p2 = e2 * inv, p3 = e3 * inv;
            float ox = p0 * v[0].x; ox = fmaf(p1, v[1].x, ox);
            ox = fmaf(p2, v[2].x, ox); ox = fmaf(p3, v[3].x, ox);
            float oy = p0 * v[0].y; oy = fmaf(p1, v[1].y, oy);
            oy = fmaf(p2, v[2].y, oy); oy = fmaf(p3, v[3].y, oy);
            *(__half2*)(O + (gRow0 + i) * Dd + head * HDIM + 2 * lane) =
                __floats2half2_rn(ox, oy);
        }
    }
}

// ---------------------------------------------------------------------------
// Warp-specialized FP16 GEMM (R13 config, unchanged) — used for projection.
// CTA 128x64, BK=64, 320 threads, 4-stage ring, 2 CTAs/SM.
// ---------------------------------------------------------------------------
#define A_TILE  16384
#define B_TILE  8192
#define STAGE_B (A_TILE + B_TILE)      // 24576
#define STAGES  4
#define GEMM_SMEM (STAGES * STAGE_B + 64)

__global__ __launch_bounds__(320, 2)
void gemm_ws_kernel(const __half* __restrict__ A, const __half* __restrict__ Bt,
                    const float* __restrict__ bias, float* __restrict__ C,
                    int N, int K)
{
    extern __shared__ char dsm[];
    const uint32_t sbase = smem_u32(dsm);
    const uint32_t mbarB = sbase + STAGES * STAGE_B;

    const int tid  = threadIdx.x;
    const int wid  = tid >> 5;
    const int lane = tid & 31;

    const int m0 = blockIdx.y * 128;
    const int n0 = blockIdx.x * 64;
    const int NC = K >> 6;

    if (tid == 0) {
#pragma unroll
        for (int s = 0; s < STAGES; ++s) {
            MBAR_INIT(mbarB + s * 16,     64);
            MBAR_INIT(mbarB + s * 16 + 8, 256);
        }
    }
    __syncthreads();

    if (wid >= 8) {
        const int pt  = tid - 256;
        const int k16 = pt & 7;
        const int rg  = pt >> 3;
        const char* aP = (const char*)A  + ((size_t)(m0 + rg) * K + k16 * 8) * 2;
        const char* bP = (const char*)Bt + ((size_t)(n0 + rg) * K + k16 * 8) * 2;
        const uint32_t sx = (uint32_t)((k16 ^ rg) << 4);
        const uint32_t aRel = (uint32_t)rg * 128 + sx;
        const uint32_t bRel = (uint32_t)rg * 128 + sx + A_TILE;
        const size_t rowStep = (size_t)(8 * K) * 2;

        int ph = 1;
        for (int c = 0; c < NC; ++c) {
            const int s = c & 3;
            MBAR_WAIT(mbarB + s * 16 + 8, ph);
            if (s == 3) ph ^= 1;
            const uint32_t base = sbase + s * STAGE_B;
            {
                const char* p = aP;
                uint32_t d = base + aRel;
#pragma unroll
                for (int it = 0; it < 16; ++it) { cpasync16(d, p); p += rowStep; d += 1024; }
            }
            {
                const char* p = bP;
                uint32_t d = base + bRel;
#pragma unroll
                for (int it = 0; it < 8; ++it) { cpasync16(d, p); p += rowStep; d += 1024; }
            }
            CPASYNC_MBAR_ARRIVE(mbarB + s * 16);
            aP += BKC * 2; bP += BKC * 2;
        }
        return;
    }

    const int warpM = wid & 3;
    const int warpN = wid >> 2;

    const int r8  = lane & 7;
    const int sel = lane >> 3;
    const int rowAdd = r8 + ((sel & 1) << 3);
    const int colAdd = sel >> 1;
    uint32_t colPart[4];
#pragma unroll
    for (int ks = 0; ks < 4; ++ks)
        colPart[ks] = (uint32_t)(((2 * ks + colAdd) ^ r8) << 4);

    uint32_t aRow[2], bRow[2];
#pragma unroll
    for (int g = 0; g < 2; ++g) {
        aRow[g] = (uint32_t)(warpM * 32 + g * 16 + rowAdd) * 128;
        bRow[g] = (uint32_t)(warpN * 32 + g * 16 + rowAdd) * 128 + A_TILE;
    }

    float acc[2][4][4];
#pragma unroll
    for (int mt = 0; mt < 2; ++mt)
#pragma unroll
        for (int nt = 0; nt < 4; ++nt)
#pragma unroll
            for (int r = 0; r < 4; ++r) acc[mt][nt][r] = 0.0f;

    uint32_t aF[2][4], bF[4][2];

    int ph = 0;
    for (int c = 0; c < NC; ++c) {
        const int s = c & 3;
        MBAR_WAIT(mbarB + s * 16, ph);
        if (s == 3) ph ^= 1;
        const uint32_t sB = sbase + s * STAGE_B;

#pragma unroll
        for (int ks = 0; ks < 4; ++ks) {
            const uint32_t cp = colPart[ks];
#pragma unroll
            for (int mt = 0; mt < 2; ++mt) {
                asm volatile("ldmatrix.sync.aligned.m8n8.x4.shared.b16 {%0,%1,%2,%3}, [%4];"
                             : "=r"(aF[mt][0]), "=r"(aF[mt][1]),
                               "=r"(aF[mt][2]), "=r"(aF[mt][3])
                             : "r"(sB + aRow[mt] + cp));
            }
#pragma unroll
            for (int g = 0; g < 2; ++g) {
                uint32_t r0, r1, r2, r3;
                asm volatile("ldmatrix.sync.aligned.m8n8.x4.shared.b16 {%0,%1,%2,%3}, [%4];"
                             : "=r"(r0), "=r"(r1), "=r"(r2), "=r"(r3)
                             : "r"(sB + bRow[g] + cp));
                bF[g * 2][0]     = r0; bF[g * 2][1]     = r2;
                bF[g * 2 + 1][0] = r1; bF[g * 2 + 1][1] = r3;
            }
#pragma unroll
            for (int mt = 0; mt < 2; ++mt)
#pragma unroll
                for (int nt = 0; nt < 4; ++nt)
                    mma_f16(acc[mt][nt], aF[mt], bF[nt]);
        }
        MBAR_ARRIVE(mbarB + s * 16 + 8);
    }

    const int col0 = n0 + warpN * 32 + 2 * (lane & 3);
    float2 bv[4];
#pragma unroll
    for (int nt = 0; nt < 4; ++nt)
        bv[nt] = *(const float2*)(bias + col0 + nt * 8);

    const int row0 = m0 + warpM * 32 + (lane >> 2);
#pragma unroll
    for (int mt = 0; mt < 2; ++mt) {
        int r = row0 + mt * 16;
#pragma unroll
        for (int nt = 0; nt < 4; ++nt) {
            int cc = col0 + nt * 8;
            *(float2*)(C + (size_t)r * N + cc) =
                make_float2(acc[mt][nt][0] + bv[nt].x, acc[mt][nt][1] + bv[nt].y);
            *(float2*)(C + (size_t)(r + 8) * N + cc) =
                make_float2(acc[mt][nt][2] + bv[nt].x, acc[mt][nt][3] + bv[nt].y);
        }
    }
}

// ---------------------------------------------------------------------------
extern "C" void kernel_launch(void* const* d_in, const int* in_sizes, int n_in,
                              void* d_out, int out_size)
{
    const float* x     = (const float*)d_in[0];
    const float* Wqkv  = (const float*)d_in[1];
    const float* bqkv  = (const float*)d_in[2];
    const float* Wproj = (const float*)d_in[3];
    const float* bproj = (const float*)d_in[4];
    float* out = (float*)d_out;

    __half *oh, *xh, *wqh, *wph;
    cudaGetSymbolAddress((void**)&oh,  g_oh);
    cudaGetSymbolAddress((void**)&xh,  g_xh);
    cudaGetSymbolAddress((void**)&wqh, g_wqh);
    cudaGetSymbolAddress((void**)&wph, g_wph);

    cudaFuncSetAttribute(qkv_attn_fused_kernel,
                         cudaFuncAttributeMaxDynamicSharedMemorySize, FUSED_SMEM);
    cudaFuncSetAttribute(gemm_ws_kernel,
                         cudaFuncAttributeMaxDynamicSharedMemorySize, GEMM_SMEM);

    // 0) x -> fp16; weights -> transposed fp16 (Wt[N][K])
    f2h_kernel<<<8192, 256>>>((const float4*)x, (uint2*)xh, MTOT * Dd / 4);
    {
        dim3 g1(NQKV / 32, Dd / 32);
        transpose_h_kernel<<<g1, 256>>>(Wqkv, wqh, Dd, NQKV);
        dim3 g2(Dd / 32, Dd / 32);
        transpose_h_kernel<<<g2, 256>>>(Wproj, wph, Dd, Dd);
    }

    // 1) fused: qkv GEMM (+bias) + block attention -> o (fp16)
    {
        dim3 grid(Hh, MTOT / 64);   // (16 heads, 512 M-tiles)
        qkv_attn_fused_kernel<<<grid, 320, FUSED_SMEM>>>(xh, wqh, bqkv, oh);
    }

    // 2) out = o @ W_proj + b_proj  (f32 out)
    {
        dim3 grid(Dd / 64, MTOT / 128);
        gemm_ws_kernel<<<grid, 320, GEMM_SMEM>>>(oh, wph, bproj, out, Dd, Dd);
    }
}